// round 7
// baseline (speedup 1.0000x reference)
#include <cuda_runtime.h>
#include <math.h>

#define BB 8
#define SS 1024
#define DD 512
#define HD 64
#define NROWS (BB*SS)
#define EPSV 1e-5f
#define SCP 1036
#define KV_FL 8704   // per KV buffer (words): max(128*68, 64*132)

// ---------------- scratch ----------------
__device__ float g_Qp[NROWS*DD];   // tf32 bits, [s][d]
__device__ float g_Kp[NROWS*DD];   // tf32 bits, [s][d]
__device__ float g_Vt[NROWS*DD];   // tf32 bits, TRANSPOSED: [bh][d][s]
__device__ float g_ao[NROWS*DD];   // exact fp32
__device__ float g_Qn[NROWS*DD];   // normed Q, tf32 bits
__device__ float g_aon[NROWS*DD];  // normed ao, tf32 bits
__device__ float g_Wt[4*DD*DD];    // tf32 weights TRANSPOSED: [n][k]
__device__ float g_sum1[BB], g_sq1[BB], g_sum2[BB], g_sq2[BB];
__device__ int   g_cnt[BB];
__device__ int   g_mask[NROWS];

// ---------------- helpers ----------------
__device__ __forceinline__ unsigned f2tf(float x) {
    unsigned r; asm("cvt.rna.tf32.f32 %0, %1;" : "=r"(r) : "f"(x)); return r;
}
__device__ __forceinline__ void mma8(float* c, unsigned a0, unsigned a1, unsigned a2, unsigned a3,
                                     unsigned b0, unsigned b1) {
    asm volatile(
        "mma.sync.aligned.m16n8k8.row.col.f32.tf32.tf32.f32 "
        "{%0,%1,%2,%3},{%4,%5,%6,%7},{%8,%9},{%0,%1,%2,%3};"
        : "+f"(c[0]), "+f"(c[1]), "+f"(c[2]), "+f"(c[3])
        : "r"(a0), "r"(a1), "r"(a2), "r"(a3), "r"(b0), "r"(b1));
}
__device__ __forceinline__ void ldsm4(unsigned addr, unsigned& r0, unsigned& r1,
                                      unsigned& r2, unsigned& r3) {
    asm volatile("ldmatrix.sync.aligned.m8n8.x4.shared.b16 {%0,%1,%2,%3}, [%4];"
                 : "=r"(r0), "=r"(r1), "=r"(r2), "=r"(r3) : "r"(addr));
}
__device__ __forceinline__ unsigned cvta_s(const void* p) {
    return (unsigned)__cvta_generic_to_shared(p);
}
#define CP16(dst_u32, src_ptr) \
    asm volatile("cp.async.cg.shared.global [%0], [%1], 16;" :: "r"(dst_u32), "l"(src_ptr))
#define CP_COMMIT() asm volatile("cp.async.commit_group;")
#define CP_WAIT1()  asm volatile("cp.async.wait_group 1;")
#define CP_WAIT0()  asm volatile("cp.async.wait_group 0;")

// ---------------- tiny kernels ----------------
// transpose + tf32: g_Wt[z][n][k] = tf32(W[k][n])
__global__ void k_cvtW(const float* __restrict__ Wq, const float* __restrict__ Wk,
                       const float* __restrict__ Wv, const float* __restrict__ Wo) {
    if (blockIdx.x == 0 && blockIdx.y == 0 && blockIdx.z == 0 && threadIdx.x < BB) {
        int t = threadIdx.x;
        g_sum1[t]=0.f; g_sq1[t]=0.f; g_sum2[t]=0.f; g_sq2[t]=0.f; g_cnt[t]=0;
    }
    __shared__ float t[32][33];
    const float* src = (blockIdx.z == 0) ? Wq : (blockIdx.z == 1) ? Wk :
                       (blockIdx.z == 2) ? Wv : Wo;
    float* dst = g_Wt + (size_t)blockIdx.z * DD * DD;
    int k0 = blockIdx.x * 32, n0 = blockIdx.y * 32;
    int c = threadIdx.x & 31, r0 = threadIdx.x >> 5;
    #pragma unroll
    for (int i = 0; i < 4; i++) {
        int r = r0 + 8 * i;
        t[r][c] = src[(size_t)(k0 + r) * DD + n0 + c];
    }
    __syncthreads();
    #pragma unroll
    for (int i = 0; i < 4; i++) {
        int r = r0 + 8 * i;
        ((unsigned*)dst)[(size_t)(n0 + r) * DD + k0 + c] = f2tf(t[c][r]);
    }
}

__global__ void k_maskstats(const float* __restrict__ Q) {
    int row = blockIdx.x;
    int t = threadIdx.x;
    float4 q = ((const float4*)(Q + (size_t)row * DD))[t];
    bool nz = (q.x != 0.f) || (q.y != 0.f) || (q.z != 0.f) || (q.w != 0.f);
    float s  = q.x + q.y + q.z + q.w;
    float s2 = q.x*q.x + q.y*q.y + q.z*q.z + q.w*q.w;
    int valid = __syncthreads_or(nz ? 1 : 0);
    #pragma unroll
    for (int o = 16; o > 0; o >>= 1) {
        s  += __shfl_xor_sync(0xffffffffu, s,  o);
        s2 += __shfl_xor_sync(0xffffffffu, s2, o);
    }
    __shared__ float rs[4], rs2[4];
    if ((t & 31) == 0) { rs[t >> 5] = s; rs2[t >> 5] = s2; }
    __syncthreads();
    if (t == 0) {
        g_mask[row] = valid;
        if (valid) {
            int b = row >> 10;
            atomicAdd(&g_cnt[b], 1);
            atomicAdd(&g_sum1[b], rs[0]+rs[1]+rs[2]+rs[3]);
            atomicAdd(&g_sq1[b],  rs2[0]+rs2[1]+rs2[2]+rs2[3]);
        }
    }
}

__global__ void k_norm(const float* __restrict__ src, float* __restrict__ dst, int which) {
    int row = blockIdx.x;
    int t = threadIdx.x;
    int b = row >> 10;
    float cntD = (float)g_cnt[b] * (float)DD;
    float sum = which ? g_sum2[b] : g_sum1[b];
    float sq  = which ? g_sq2[b]  : g_sq1[b];
    float mean = (cntD > 0.f) ? sum / cntD : 0.f;
    float var  = (cntD > 0.f) ? sq / cntD - mean * mean : 0.f;
    if (var < 0.f) var = 0.f;
    float rstd = rsqrtf(var + EPSV);
    float sc = g_mask[row] ? rstd : 0.f;
    float mm = mean * sc;
    float4 v = ((const float4*)(src + (size_t)row * DD))[t];
    uint4 u;
    u.x = f2tf(fmaf(v.x, sc, -mm)); u.y = f2tf(fmaf(v.y, sc, -mm));
    u.z = f2tf(fmaf(v.z, sc, -mm)); u.w = f2tf(fmaf(v.w, sc, -mm));
    ((uint4*)(dst + (size_t)row * DD))[t] = u;
}

// ============ tf32 GEMM body with ldmatrix ============
// BM=128, BN=64, BK=32; 256 thr = 8 warps (4m x 2n), warp tile 32x32.
// A smem [m][k] stride 36; B smem [n][k] stride 36 (weights are pre-transposed).
struct GemmOut { float c[2][4][4]; };

__device__ __forceinline__ void gemm_body(
    const float* __restrict__ Asrc, const float* __restrict__ Bsrc,
    int m0, int n0, float* smq, GemmOut& R)
{
    float* As0 = smq;              // 128*36
    float* As1 = smq + 4608;
    float* Bs0 = smq + 9216;       // 64*36
    float* Bs1 = smq + 9216 + 2304;

    int tid = threadIdx.x;
    int wid = tid >> 5, lane = tid & 31;
    int wm = wid >> 1, wn = wid & 1;
    int m2 = lane >> 3, r8 = lane & 7;

    unsigned uA0 = cvta_s(As0), uA1 = cvta_s(As1);
    unsigned uB0 = cvta_s(Bs0), uB1 = cvta_s(Bs1);

    // ldsm row offsets (words), invariant over s
    int rowA0 = (wm * 32 +      (m2 & 1) * 8 + r8) * 36 + (m2 >> 1) * 4;
    int rowA1 = (wm * 32 + 16 + (m2 & 1) * 8 + r8) * 36 + (m2 >> 1) * 4;
    int rowB0 = (wn * 32 +      (m2 >> 1) * 8 + r8) * 36 + (m2 & 1) * 4;
    int rowB1 = (wn * 32 + 16 + (m2 >> 1) * 8 + r8) * 36 + (m2 & 1) * 4;

    int arow = tid >> 3, ac8 = tid & 7;   // A loader: 4 iters
    int brow = tid >> 3, bc8 = tid & 7;   // B loader: 2 iters over 64 rows

    #pragma unroll
    for (int mi = 0; mi < 2; mi++)
        #pragma unroll
        for (int ni = 0; ni < 4; ni++)
            #pragma unroll
            for (int j = 0; j < 4; j++) R.c[mi][ni][j] = 0.f;

    {
        #pragma unroll
        for (int i = 0; i < 4; i++) {
            int row = arow + 32 * i;
            CP16(uA0 + (row * 36 + ac8 * 4) * 4, Asrc + (size_t)(m0 + row) * 512 + ac8 * 4);
        }
        #pragma unroll
        for (int i = 0; i < 2; i++) {
            int row = brow + 32 * i;
            CP16(uB0 + (row * 36 + bc8 * 4) * 4, Bsrc + (size_t)(n0 + row) * 512 + bc8 * 4);
        }
        CP_COMMIT();
    }

    for (int kc = 0; kc < 16; kc++) {
        unsigned uAf = (kc & 1) ? uA1 : uA0;
        unsigned uBf = (kc & 1) ? uB1 : uB0;
        if (kc < 15) {
            unsigned nA = (kc & 1) ? uA0 : uA1;
            unsigned nB = (kc & 1) ? uB0 : uB1;
            int k0 = (kc + 1) * 32;
            #pragma unroll
            for (int i = 0; i < 4; i++) {
                int row = arow + 32 * i;
                CP16(nA + (row * 36 + ac8 * 4) * 4, Asrc + (size_t)(m0 + row) * 512 + k0 + ac8 * 4);
            }
            #pragma unroll
            for (int i = 0; i < 2; i++) {
                int row = brow + 32 * i;
                CP16(nB + (row * 36 + bc8 * 4) * 4, Bsrc + (size_t)(n0 + row) * 512 + k0 + bc8 * 4);
            }
            CP_COMMIT();
            CP_WAIT1();
        } else {
            CP_WAIT0();
        }
        __syncthreads();

        #pragma unroll
        for (int s = 0; s < 4; s++) {
            unsigned a[2][4], bb[4][2];
            ldsm4(uAf + (rowA0 + s * 8) * 4, a[0][0], a[0][1], a[0][2], a[0][3]);
            ldsm4(uAf + (rowA1 + s * 8) * 4, a[1][0], a[1][1], a[1][2], a[1][3]);
            ldsm4(uBf + (rowB0 + s * 8) * 4, bb[0][0], bb[0][1], bb[1][0], bb[1][1]);
            ldsm4(uBf + (rowB1 + s * 8) * 4, bb[2][0], bb[2][1], bb[3][0], bb[3][1]);
            #pragma unroll
            for (int mi = 0; mi < 2; mi++)
                #pragma unroll
                for (int ni = 0; ni < 4; ni++)
                    mma8(R.c[mi][ni], a[mi][0], a[mi][1], a[mi][2], a[mi][3],
                         bb[ni][0], bb[ni][1]);
        }
        __syncthreads();
    }
}

// ---------------- QKV ----------------
__global__ __launch_bounds__(256, 3)
void k_qkv(const float* __restrict__ bq, const float* __restrict__ bk,
           const float* __restrict__ bv) {
    extern __shared__ float smq[];
    int z = blockIdx.z;
    const float* bias = (z == 0) ? bq : (z == 1) ? bk : bv;
    const float* Bsrc = g_Wt + (size_t)z * DD * DD;

    int n0 = blockIdx.x * 64, m0 = blockIdx.y * 128;
    int tid = threadIdx.x;
    int wid = tid >> 5, lane = tid & 31, g = lane >> 2, tig = lane & 3;
    int wm = wid >> 1, wn = wid & 1;

    GemmOut R;
    gemm_body(g_Qn, Bsrc, m0, n0, smq, R);

    if (z < 2) {
        float* outp = (z == 0) ? g_Qp : g_Kp;
        #pragma unroll
        for (int mi = 0; mi < 2; mi++) {
            int r0 = m0 + wm * 32 + mi * 16 + g;
            float mk0 = g_mask[r0]     ? 1.f : 0.f;
            float mk1 = g_mask[r0 + 8] ? 1.f : 0.f;
            #pragma unroll
            for (int ni = 0; ni < 4; ni++) {
                int col = n0 + wn * 32 + ni * 8 + tig * 2;
                float b0v = bias[col], b1v = bias[col + 1];
                uint2 o0 = make_uint2(f2tf((R.c[mi][ni][0] + b0v) * mk0),
                                      f2tf((R.c[mi][ni][1] + b1v) * mk0));
                uint2 o1 = make_uint2(f2tf((R.c[mi][ni][2] + b0v) * mk1),
                                      f2tf((R.c[mi][ni][3] + b1v) * mk1));
                *(uint2*)(outp + (size_t)r0 * 512 + col)       = o0;
                *(uint2*)(outp + (size_t)(r0 + 8) * 512 + col) = o1;
            }
        }
    } else {
        // V: write transposed g_Vt[bh][d][s]
        #pragma unroll
        for (int mi = 0; mi < 2; mi++) {
            int r0 = m0 + wm * 32 + mi * 16 + g;      // seq global
            int bidx = r0 >> 10, s_ = r0 & 1023;
            float mk0 = g_mask[r0]     ? 1.f : 0.f;
            float mk1 = g_mask[r0 + 8] ? 1.f : 0.f;
            #pragma unroll
            for (int ni = 0; ni < 4; ni++) {
                int col = n0 + wn * 32 + ni * 8 + tig * 2;
                int h_ = col >> 6, dl = col & 63;
                float b0v = bias[col], b1v = bias[col + 1];
                unsigned* vt0 = (unsigned*)g_Vt + (((size_t)(bidx * 8 + h_) * 64 + dl) << 10);
                unsigned* vt1 = vt0 + 1024;
                vt0[s_]     = f2tf((R.c[mi][ni][0] + b0v) * mk0);
                vt1[s_]     = f2tf((R.c[mi][ni][1] + b1v) * mk0);
                vt0[s_ + 8] = f2tf((R.c[mi][ni][2] + b0v) * mk1);
                vt1[s_ + 8] = f2tf((R.c[mi][ni][3] + b1v) * mk1);
            }
        }
    }
}

// ---------------- output GEMM ----------------
__global__ __launch_bounds__(256, 3)
void k_out(const float* __restrict__ bo, float* __restrict__ out) {
    extern __shared__ float smq[];
    int n0 = blockIdx.x * 64, m0 = blockIdx.y * 128;
    int tid = threadIdx.x;
    int wid = tid >> 5, lane = tid & 31, g = lane >> 2, tig = lane & 3;
    int wm = wid >> 1, wn = wid & 1;

    GemmOut R;
    gemm_body(g_aon, g_Wt + (size_t)3 * DD * DD, m0, n0, smq, R);

    #pragma unroll
    for (int mi = 0; mi < 2; mi++) {
        int r0 = m0 + wm * 32 + mi * 16 + g;
        #pragma unroll
        for (int ni = 0; ni < 4; ni++) {
            int col = n0 + wn * 32 + ni * 8 + tig * 2;
            float b0v = bo[col], b1v = bo[col + 1];
            float2 a0 = *(const float2*)(g_ao + (size_t)r0 * 512 + col);
            float2 a1 = *(const float2*)(g_ao + (size_t)(r0 + 8) * 512 + col);
            float2 o0 = make_float2(a0.x + fmaxf(R.c[mi][ni][0] + b0v, 0.f),
                                    a0.y + fmaxf(R.c[mi][ni][1] + b1v, 0.f));
            float2 o1 = make_float2(a1.x + fmaxf(R.c[mi][ni][2] + b0v, 0.f),
                                    a1.y + fmaxf(R.c[mi][ni][3] + b1v, 0.f));
            *(float2*)(out + (size_t)r0 * 512 + col)       = o0;
            *(float2*)(out + (size_t)(r0 + 8) * 512 + col) = o1;
        }
    }
}

// ---------------- attention ----------------
__global__ __launch_bounds__(512)
void k_attn(const float* __restrict__ Q, float* __restrict__ w_out) {
    extern __shared__ float sm[];
    float*    sc  = sm;                            // 32*1036
    unsigned* scU = (unsigned*)sc;
    float*    kvb = sc + 32 * SCP;                 // 2*KV_FL
    unsigned* qs  = (unsigned*)(kvb + 2 * KV_FL);  // 32*68
    float*    red = (float*)(qs + 32 * 68);        // 32

    int tid = threadIdx.x;
    int wid = tid >> 5, lane = tid & 31, g = lane >> 2, tig = lane & 3;
    int m2 = lane >> 3, r8 = lane & 7;
    int bh = blockIdx.y, b = bh >> 3, h = bh & 7;
    int q0 = blockIdx.x * 32;
    size_t baseQ = ((size_t)b * SS + q0) * DD + h * HD;
    size_t baseK = ((size_t)b * SS) * DD + h * HD;
    size_t baseVt = (size_t)bh * HD * SS;
    const int bS = b * SS;

    unsigned uKV0 = cvta_s(kvb), uKV1 = cvta_s(kvb + KV_FL);
    unsigned uQS = cvta_s(qs), uSC = cvta_s(sc);
    int lr = tid >> 4, lc4 = tid & 15;

    // prefetch K chunk 0 ([key][d], stride 68)
    #pragma unroll
    for (int i = 0; i < 4; i++) {
        int row = lr + 32 * i;
        CP16(uKV0 + (row * 68 + lc4 * 4) * 4, g_Kp + baseK + (size_t)row * DD + lc4 * 4);
    }
    CP_COMMIT();

    // q tile (tf32 bits) -> smem
    *(uint4*)&qs[lr * 68 + lc4 * 4] =
        *(const uint4*)(g_Qp + baseQ + (size_t)lr * DD + lc4 * 4);
    __syncthreads();

    // preload A fragments (Q) into registers via ldsm
    int nslot = wid >> 1, mh = wid & 1;
    unsigned areg[8][4];
    {
        int rowQ = (mh * 16 + (m2 & 1) * 8 + r8) * 68 + (m2 >> 1) * 4;
        #pragma unroll
        for (int s = 0; s < 8; s++)
            ldsm4(uQS + (rowQ + s * 8) * 4, areg[s][0], areg[s][1], areg[s][2], areg[s][3]);
    }

    // ---- scores ----
    int rowKB = (nslot * 16 + (m2 >> 1) * 8 + r8) * 68 + (m2 & 1) * 4;
    for (int kt = 0; kt < 8; kt++) {
        unsigned uKVf = (kt & 1) ? uKV1 : uKV0;
        if (kt < 7) {
            unsigned nxt = (kt & 1) ? uKV0 : uKV1;
            #pragma unroll
            for (int i = 0; i < 4; i++) {
                int row = lr + 32 * i;
                CP16(nxt + (row * 68 + lc4 * 4) * 4,
                     g_Kp + baseK + (size_t)((kt + 1) * 128 + row) * DD + lc4 * 4);
            }
            CP_COMMIT();
            CP_WAIT1();
        } else {
            CP_WAIT0();
        }
        __syncthreads();

        float cc[2][4];
        #pragma unroll
        for (int nf = 0; nf < 2; nf++)
            #pragma unroll
            for (int j = 0; j < 4; j++) cc[nf][j] = 0.f;

        #pragma unroll
        for (int s = 0; s < 8; s++) {
            unsigned bb[2][2];
            ldsm4(uKVf + (rowKB + s * 8) * 4, bb[0][0], bb[0][1], bb[1][0], bb[1][1]);
            mma8(cc[0], areg[s][0], areg[s][1], areg[s][2], areg[s][3], bb[0][0], bb[0][1]);
            mma8(cc[1], areg[s][0], areg[s][1], areg[s][2], areg[s][3], bb[1][0], bb[1][1]);
        }
        #pragma unroll
        for (int nf = 0; nf < 2; nf++) {
            int gc = kt * 128 + nslot * 16 + nf * 8 + tig * 2;
            bool k0v = g_mask[bS + gc] != 0;
            bool k1v = g_mask[bS + gc + 1] != 0;
            int r = mh * 16 + g;
            float2 v0 = make_float2(k0v ? cc[nf][0] * 0.125f : -1e30f,
                                    k1v ? cc[nf][1] * 0.125f : -1e30f);
            float2 v1 = make_float2(k0v ? cc[nf][2] * 0.125f : -1e30f,
                                    k1v ? cc[nf][3] * 0.125f : -1e30f);
            *(float2*)&sc[r * SCP + gc]       = v0;
            *(float2*)&sc[(r + 8) * SCP + gc] = v1;
        }
        __syncthreads();
    }

    // prefetch V^T chunk 0 ([d][s-chunk], 64 rows x 128 words, stride 132)
    #pragma unroll
    for (int i = 0; i < 4; i++) {
        int f = tid + 512 * i;
        int row = f >> 5, c4 = f & 31;
        CP16(uKV0 + (row * 132 + c4 * 4) * 4,
             g_Vt + baseVt + (size_t)row * SS + c4 * 4);
    }
    CP_COMMIT();

    // ---- softmax (no max pass; masked scores are -1e30 -> exp = 0) ----
    {
        int row = tid >> 4, l = tid & 15;
        float* srow = sc + row * SCP;
        float sum = 0.f;
        #pragma unroll
        for (int j = 0; j < 16; j++) {
            float4 v = *(float4*)&srow[(l + 16 * j) * 4];
            v.x = __expf(v.x); v.y = __expf(v.y); v.z = __expf(v.z); v.w = __expf(v.w);
            sum += v.x + v.y + v.z + v.w;
            *(float4*)&srow[(l + 16 * j) * 4] = v;
        }
        #pragma unroll
        for (int o = 8; o > 0; o >>= 1) sum += __shfl_xor_sync(0xffffffffu, sum, o);
        float inv = g_mask[bS + q0 + row] ? (1.0f / sum) : 0.f;

        float* wrow = w_out + ((size_t)bh * SS + q0 + row) * SS;
        unsigned* urow = scU + row * SCP;
        #pragma unroll
        for (int j = 0; j < 16; j++) {
            int c = (l + 16 * j) * 4;
            float4 v = *(float4*)&srow[c];
            v.x *= inv; v.y *= inv; v.z *= inv; v.w *= inv;
            *(float4*)(wrow + c) = v;
            uint4 u; u.x = f2tf(v.x); u.y = f2tf(v.y); u.z = f2tf(v.z); u.w = f2tf(v.w);
            *(uint4*)&urow[c] = u;
        }
    }
    __syncthreads();

    // ---- attnV: 16 warps = 8 k-splits x 2 n-slots; ldsm for A and B ----
    int ksl = wid & 7, nsl = wid >> 3;
    int rowPA0 = (     (m2 & 1) * 8 + r8) * SCP + (m2 >> 1) * 4;
    int rowPA1 = (16 + (m2 & 1) * 8 + r8) * SCP + (m2 >> 1) * 4;
    int rowVB0 = (nsl * 32 +      (m2 >> 1) * 8 + r8) * 132 + (m2 & 1) * 4;
    int rowVB1 = (nsl * 32 + 16 + (m2 >> 1) * 8 + r8) * 132 + (m2 & 1) * 4;

    float acc[2][4][4];
    #pragma unroll
    for (int mi = 0; mi < 2; mi++)
        #pragma unroll
        for (int nf = 0; nf < 4; nf++)
            #pragma unroll
            for (int j = 0; j < 4; j++) acc[mi][nf][j] = 0.f;

    for (int vt = 0; vt < 8; vt++) {
        unsigned uKVf = (vt & 1) ? uKV1 : uKV0;
        if (vt < 7) {
            unsigned nxt = (vt & 1) ? uKV0 : uKV1;
            #pragma unroll
            for (int i = 0; i < 4; i++) {
                int f = tid + 512 * i;
                int row = f >> 5, c4 = f & 31;
                CP16(nxt + (row * 132 + c4 * 4) * 4,
                     g_Vt + baseVt + (size_t)row * SS + (vt + 1) * 128 + c4 * 4);
            }
            CP_COMMIT();
            CP_WAIT1();
        } else {
            CP_WAIT0();
        }
        __syncthreads();

        #pragma unroll
        for (int s = 0; s < 2; s++) {
            int kk = vt * 128 + ksl * 16 + s * 8;   // global k for A (score panel)
            int kl = ksl * 16 + s * 8;              // local k for B (V^T tile)
            unsigned a[2][4], bb[4][2];
            ldsm4(uSC + (rowPA0 + kk) * 4, a[0][0], a[0][1], a[0][2], a[0][3]);
            ldsm4(uSC + (rowPA1 + kk) * 4, a[1][0], a[1][1], a[1][2], a[1][3]);
            ldsm4(uKVf + (rowVB0 + kl) * 4, bb[0][0], bb[0][1], bb[1][0], bb[1][1]);
            ldsm4(uKVf + (rowVB1 + kl) * 4, bb[2][0], bb[2][1], bb[3][0], bb[3][1]);
            #pragma unroll
            for (int nf = 0; nf < 4; nf++) {
                mma8(acc[0][nf], a[0][0], a[0][1], a[0][2], a[0][3], bb[nf][0], bb[nf][1]);
                mma8(acc[1][nf], a[1][0], a[1][1], a[1][2], a[1][3], bb[nf][0], bb[nf][1]);
            }
        }
        __syncthreads();
    }

    // ---- reduce 8 k-splits via kvb (8 regions of 32x68) ----
    float* at = kvb;
    #pragma unroll
    for (int mi = 0; mi < 2; mi++) {
        int r = mi * 16 + g;
        #pragma unroll
        for (int nf = 0; nf < 4; nf++) {
            int col = nsl * 32 + nf * 8 + tig * 2;
            *(float2*)&at[ksl * 2176 + r * 68 + col]       = make_float2(acc[mi][nf][0], acc[mi][nf][1]);
            *(float2*)&at[ksl * 2176 + (r + 8) * 68 + col] = make_float2(acc[mi][nf][2], acc[mi][nf][3]);
        }
    }
    __syncthreads();

    // ---- epilogue: attn_out = attn + Q; stats2 ----
    {
        float4 o = make_float4(0.f, 0.f, 0.f, 0.f);
        #pragma unroll
        for (int k = 0; k < 8; k++) {
            float4 p = *(const float4*)&at[k * 2176 + lr * 68 + lc4 * 4];
            o.x += p.x; o.y += p.y; o.z += p.z; o.w += p.w;
        }
        size_t gaddr = baseQ + (size_t)lr * DD + lc4 * 4;
        float4 q4 = *(const float4*)(Q + gaddr);
        o.x += q4.x; o.y += q4.y; o.z += q4.z; o.w += q4.w;
        *(float4*)(g_ao + gaddr) = o;
        float t1 = o.x + o.y + o.z + o.w;
        float t2 = o.x*o.x + o.y*o.y + o.z*o.z + o.w*o.w;
        #pragma unroll
        for (int off = 16; off > 0; off >>= 1) {
            t1 += __shfl_xor_sync(0xffffffffu, t1, off);
            t2 += __shfl_xor_sync(0xffffffffu, t2, off);
        }
        if (lane == 0) { red[wid] = t1; red[16 + wid] = t2; }
    }
    __syncthreads();
    if (tid == 0) {
        float S1 = 0.f, S2 = 0.f;
        #pragma unroll
        for (int i = 0; i < 16; i++) { S1 += red[i]; S2 += red[16 + i]; }
        atomicAdd(&g_sum2[b], S1);
        atomicAdd(&g_sq2[b], S2);
    }
}

// ---------------- launch ----------------
extern "C" void kernel_launch(void* const* d_in, const int* in_sizes, int n_in,
                              void* d_out, int out_size) {
    const float* Q  = (const float*)d_in[0];
    const float* Wq = (const float*)d_in[1];
    const float* bq = (const float*)d_in[2];
    const float* Wk = (const float*)d_in[3];
    const float* bk = (const float*)d_in[4];
    const float* Wv = (const float*)d_in[5];
    const float* bv = (const float*)d_in[6];
    const float* Wo = (const float*)d_in[7];
    const float* bo = (const float*)d_in[8];

    float* out = (float*)d_out;
    float* w   = out + (size_t)BB * SS * DD;

    float* g_ao_ptr;  cudaGetSymbolAddress((void**)&g_ao_ptr,  g_ao);
    float* g_Qn_ptr;  cudaGetSymbolAddress((void**)&g_Qn_ptr,  g_Qn);
    float* g_aon_ptr; cudaGetSymbolAddress((void**)&g_aon_ptr, g_aon);

    const int GEMM_SMEM = (2 * 4608 + 2 * 2304) * 4;
    const int ATTN_SMEM = (32 * SCP + 2 * KV_FL + 32 * 68 + 32) * 4;
    cudaFuncSetAttribute(k_qkv,  cudaFuncAttributeMaxDynamicSharedMemorySize, GEMM_SMEM);
    cudaFuncSetAttribute(k_out,  cudaFuncAttributeMaxDynamicSharedMemorySize, GEMM_SMEM);
    cudaFuncSetAttribute(k_attn, cudaFuncAttributeMaxDynamicSharedMemorySize, ATTN_SMEM);

    k_cvtW<<<dim3(16, 16, 4), 256>>>(Wq, Wk, Wv, Wo);
    k_maskstats<<<NROWS, 128>>>(Q);
    k_norm<<<NROWS, 128>>>(Q, g_Qn_ptr, 0);
    k_qkv<<<dim3(8, 64, 3), 256, GEMM_SMEM>>>(bq, bk, bv);
    k_attn<<<dim3(32, 64), 512, ATTN_SMEM>>>(Q, w);
    k_norm<<<NROWS, 128>>>(g_ao_ptr, g_aon_ptr, 1);
    k_out<<<dim3(8, 64), 256, GEMM_SMEM>>>(bo, out);
}

// round 8
// speedup vs baseline: 1.0223x; 1.0223x over previous
#include <cuda_runtime.h>
#include <math.h>

#define BB 8
#define SS 1024
#define DD 512
#define HD 64
#define NROWS (BB*SS)
#define EPSV 1e-5f
#define SCP 1036
#define KVW 4352     // words per KV buffer (64 rows x 68)

// ---------------- scratch ----------------
__device__ float g_Qp[NROWS*DD];   // tf32 bits, [s][d]
__device__ float g_Kp[NROWS*DD];   // tf32 bits, [s][d]
__device__ float g_Vt[NROWS*DD];   // tf32 bits, TRANSPOSED: [bh][d][s]
__device__ float g_ao[NROWS*DD];   // exact fp32
__device__ float g_Qn[NROWS*DD];   // normed Q, tf32 bits
__device__ float g_aon[NROWS*DD];  // normed ao, tf32 bits
__device__ float g_Wt[4*DD*DD];    // tf32 weights TRANSPOSED: [n][k]
__device__ float g_sum1[BB], g_sq1[BB], g_sum2[BB], g_sq2[BB];
__device__ int   g_cnt[BB];
__device__ int   g_mask[NROWS];

// ---------------- helpers ----------------
__device__ __forceinline__ unsigned f2tf(float x) {
    unsigned r; asm("cvt.rna.tf32.f32 %0, %1;" : "=r"(r) : "f"(x)); return r;
}
__device__ __forceinline__ void mma8(float* c, unsigned a0, unsigned a1, unsigned a2, unsigned a3,
                                     unsigned b0, unsigned b1) {
    asm volatile(
        "mma.sync.aligned.m16n8k8.row.col.f32.tf32.tf32.f32 "
        "{%0,%1,%2,%3},{%4,%5,%6,%7},{%8,%9},{%0,%1,%2,%3};"
        : "+f"(c[0]), "+f"(c[1]), "+f"(c[2]), "+f"(c[3])
        : "r"(a0), "r"(a1), "r"(a2), "r"(a3), "r"(b0), "r"(b1));
}
__device__ __forceinline__ void ldsm4(unsigned addr, unsigned& r0, unsigned& r1,
                                      unsigned& r2, unsigned& r3) {
    asm volatile("ldmatrix.sync.aligned.m8n8.x4.shared.b16 {%0,%1,%2,%3}, [%4];"
                 : "=r"(r0), "=r"(r1), "=r"(r2), "=r"(r3) : "r"(addr));
}
__device__ __forceinline__ unsigned cvta_s(const void* p) {
    return (unsigned)__cvta_generic_to_shared(p);
}
#define CP16(dst_u32, src_ptr) \
    asm volatile("cp.async.cg.shared.global [%0], [%1], 16;" :: "r"(dst_u32), "l"(src_ptr))
#define CP_COMMIT() asm volatile("cp.async.commit_group;")
#define CP_WAIT2()  asm volatile("cp.async.wait_group 2;")
#define CP_WAIT0()  asm volatile("cp.async.wait_group 0;")

// ---------------- tiny kernels ----------------
__global__ void k_cvtW(const float* __restrict__ Wq, const float* __restrict__ Wk,
                       const float* __restrict__ Wv, const float* __restrict__ Wo) {
    if (blockIdx.x == 0 && blockIdx.y == 0 && blockIdx.z == 0 && threadIdx.x < BB) {
        int t = threadIdx.x;
        g_sum1[t]=0.f; g_sq1[t]=0.f; g_sum2[t]=0.f; g_sq2[t]=0.f; g_cnt[t]=0;
    }
    __shared__ float t[32][33];
    const float* src = (blockIdx.z == 0) ? Wq : (blockIdx.z == 1) ? Wk :
                       (blockIdx.z == 2) ? Wv : Wo;
    float* dst = g_Wt + (size_t)blockIdx.z * DD * DD;
    int k0 = blockIdx.x * 32, n0 = blockIdx.y * 32;
    int c = threadIdx.x & 31, r0 = threadIdx.x >> 5;
    #pragma unroll
    for (int i = 0; i < 4; i++) {
        int r = r0 + 8 * i;
        t[r][c] = src[(size_t)(k0 + r) * DD + n0 + c];
    }
    __syncthreads();
    #pragma unroll
    for (int i = 0; i < 4; i++) {
        int r = r0 + 8 * i;
        ((unsigned*)dst)[(size_t)(n0 + r) * DD + k0 + c] = f2tf(t[c][r]);
    }
}

__global__ void k_maskstats(const float* __restrict__ Q) {
    int row = blockIdx.x;
    int t = threadIdx.x;
    float4 q = ((const float4*)(Q + (size_t)row * DD))[t];
    bool nz = (q.x != 0.f) || (q.y != 0.f) || (q.z != 0.f) || (q.w != 0.f);
    float s  = q.x + q.y + q.z + q.w;
    float s2 = q.x*q.x + q.y*q.y + q.z*q.z + q.w*q.w;
    int valid = __syncthreads_or(nz ? 1 : 0);
    #pragma unroll
    for (int o = 16; o > 0; o >>= 1) {
        s  += __shfl_xor_sync(0xffffffffu, s,  o);
        s2 += __shfl_xor_sync(0xffffffffu, s2, o);
    }
    __shared__ float rs[4], rs2[4];
    if ((t & 31) == 0) { rs[t >> 5] = s; rs2[t >> 5] = s2; }
    __syncthreads();
    if (t == 0) {
        g_mask[row] = valid;
        if (valid) {
            int b = row >> 10;
            atomicAdd(&g_cnt[b], 1);
            atomicAdd(&g_sum1[b], rs[0]+rs[1]+rs[2]+rs[3]);
            atomicAdd(&g_sq1[b],  rs2[0]+rs2[1]+rs2[2]+rs2[3]);
        }
    }
}

__global__ void k_norm(const float* __restrict__ src, float* __restrict__ dst, int which) {
    int row = blockIdx.x;
    int t = threadIdx.x;
    int b = row >> 10;
    float cntD = (float)g_cnt[b] * (float)DD;
    float sum = which ? g_sum2[b] : g_sum1[b];
    float sq  = which ? g_sq2[b]  : g_sq1[b];
    float mean = (cntD > 0.f) ? sum / cntD : 0.f;
    float var  = (cntD > 0.f) ? sq / cntD - mean * mean : 0.f;
    if (var < 0.f) var = 0.f;
    float rstd = rsqrtf(var + EPSV);
    float sc = g_mask[row] ? rstd : 0.f;
    float mm = mean * sc;
    float4 v = ((const float4*)(src + (size_t)row * DD))[t];
    uint4 u;
    u.x = f2tf(fmaf(v.x, sc, -mm)); u.y = f2tf(fmaf(v.y, sc, -mm));
    u.z = f2tf(fmaf(v.z, sc, -mm)); u.w = f2tf(fmaf(v.w, sc, -mm));
    ((uint4*)(dst + (size_t)row * DD))[t] = u;
}

// ============ tf32 GEMM body: BM=128, BN=128, BK=32; 8 warps (4m x 2n), warp 32x64 ============
struct GemmOut { float c[2][8][4]; };

__device__ __forceinline__ void gemm_body(
    const float* __restrict__ Asrc, const float* __restrict__ Bsrc,
    int m0, int n0, float* smq, GemmOut& R)
{
    float* As0 = smq;               // 128*36
    float* As1 = smq + 4608;
    float* Bs0 = smq + 9216;        // 128*36
    float* Bs1 = smq + 13824;

    int tid = threadIdx.x;
    int wid = tid >> 5, lane = tid & 31;
    int wm = wid >> 1, wn = wid & 1;
    int m2 = lane >> 3, r8 = lane & 7;

    unsigned uA0 = cvta_s(As0), uA1 = cvta_s(As1);
    unsigned uB0 = cvta_s(Bs0), uB1 = cvta_s(Bs1);

    int rowA0 = (wm * 32 +      (m2 & 1) * 8 + r8) * 36 + (m2 >> 1) * 4;
    int rowA1 = rowA0 + 16 * 36;
    int rowB[4];
    #pragma unroll
    for (int nq = 0; nq < 4; nq++)
        rowB[nq] = (wn * 64 + nq * 16 + (m2 >> 1) * 8 + r8) * 36 + (m2 & 1) * 4;

    int arow = tid >> 3, c8 = tid & 7;

    #pragma unroll
    for (int mi = 0; mi < 2; mi++)
        #pragma unroll
        for (int ni = 0; ni < 8; ni++)
            #pragma unroll
            for (int j = 0; j < 4; j++) R.c[mi][ni][j] = 0.f;

    // prologue: chunk 0
    #pragma unroll
    for (int i = 0; i < 4; i++) {
        int row = arow + 32 * i;
        CP16(uA0 + (row * 36 + c8 * 4) * 4, Asrc + (size_t)(m0 + row) * 512 + c8 * 4);
        CP16(uB0 + (row * 36 + c8 * 4) * 4, Bsrc + (size_t)(n0 + row) * 512 + c8 * 4);
    }
    CP_COMMIT();

    for (int kc = 0; kc < 16; kc++) {
        CP_WAIT0();
        __syncthreads();
        if (kc < 15) {
            unsigned nA = (kc & 1) ? uA0 : uA1;
            unsigned nB = (kc & 1) ? uB0 : uB1;
            int k0 = (kc + 1) * 32;
            #pragma unroll
            for (int i = 0; i < 4; i++) {
                int row = arow + 32 * i;
                CP16(nA + (row * 36 + c8 * 4) * 4, Asrc + (size_t)(m0 + row) * 512 + k0 + c8 * 4);
                CP16(nB + (row * 36 + c8 * 4) * 4, Bsrc + (size_t)(n0 + row) * 512 + k0 + c8 * 4);
            }
        }
        CP_COMMIT();

        unsigned uAf = (kc & 1) ? uA1 : uA0;
        unsigned uBf = (kc & 1) ? uB1 : uB0;
        #pragma unroll
        for (int s = 0; s < 4; s++) {
            unsigned a[2][4], bb[8][2];
            ldsm4(uAf + (rowA0 + s * 8) * 4, a[0][0], a[0][1], a[0][2], a[0][3]);
            ldsm4(uAf + (rowA1 + s * 8) * 4, a[1][0], a[1][1], a[1][2], a[1][3]);
            #pragma unroll
            for (int nq = 0; nq < 4; nq++)
                ldsm4(uBf + (rowB[nq] + s * 8) * 4,
                      bb[nq*2][0], bb[nq*2][1], bb[nq*2+1][0], bb[nq*2+1][1]);
            #pragma unroll
            for (int mi = 0; mi < 2; mi++)
                #pragma unroll
                for (int ni = 0; ni < 8; ni++)
                    mma8(R.c[mi][ni], a[mi][0], a[mi][1], a[mi][2], a[mi][3],
                         bb[ni][0], bb[ni][1]);
        }
    }
}

// ---------------- QKV ----------------
__global__ __launch_bounds__(256, 2)
void k_qkv(const float* __restrict__ bq, const float* __restrict__ bk,
           const float* __restrict__ bv) {
    extern __shared__ float smq[];
    int z = blockIdx.z;
    const float* bias = (z == 0) ? bq : (z == 1) ? bk : bv;
    const float* Bsrc = g_Wt + (size_t)z * DD * DD;

    int n0 = blockIdx.x * 128, m0 = blockIdx.y * 128;
    int tid = threadIdx.x;
    int wid = tid >> 5, lane = tid & 31, g = lane >> 2, tig = lane & 3;
    int wm = wid >> 1, wn = wid & 1;

    GemmOut R;
    gemm_body(g_Qn, Bsrc, m0, n0, smq, R);

    if (z < 2) {
        float* outp = (z == 0) ? g_Qp : g_Kp;
        #pragma unroll
        for (int mi = 0; mi < 2; mi++) {
            int r0 = m0 + wm * 32 + mi * 16 + g;
            float mk0 = g_mask[r0]     ? 1.f : 0.f;
            float mk1 = g_mask[r0 + 8] ? 1.f : 0.f;
            #pragma unroll
            for (int ni = 0; ni < 8; ni++) {
                int col = n0 + wn * 64 + ni * 8 + tig * 2;
                float b0v = bias[col], b1v = bias[col + 1];
                uint2 o0 = make_uint2(f2tf((R.c[mi][ni][0] + b0v) * mk0),
                                      f2tf((R.c[mi][ni][1] + b1v) * mk0));
                uint2 o1 = make_uint2(f2tf((R.c[mi][ni][2] + b0v) * mk1),
                                      f2tf((R.c[mi][ni][3] + b1v) * mk1));
                *(uint2*)(outp + (size_t)r0 * 512 + col)       = o0;
                *(uint2*)(outp + (size_t)(r0 + 8) * 512 + col) = o1;
            }
        }
    } else {
        #pragma unroll
        for (int mi = 0; mi < 2; mi++) {
            int r0 = m0 + wm * 32 + mi * 16 + g;
            int bidx = r0 >> 10, s_ = r0 & 1023;
            float mk0 = g_mask[r0]     ? 1.f : 0.f;
            float mk1 = g_mask[r0 + 8] ? 1.f : 0.f;
            #pragma unroll
            for (int ni = 0; ni < 8; ni++) {
                int col = n0 + wn * 64 + ni * 8 + tig * 2;
                int h_ = col >> 6, dl = col & 63;
                float b0v = bias[col], b1v = bias[col + 1];
                unsigned* vt0 = (unsigned*)g_Vt + (((size_t)(bidx * 8 + h_) * 64 + dl) << 10);
                unsigned* vt1 = vt0 + 1024;
                vt0[s_]     = f2tf((R.c[mi][ni][0] + b0v) * mk0);
                vt1[s_]     = f2tf((R.c[mi][ni][1] + b1v) * mk0);
                vt0[s_ + 8] = f2tf((R.c[mi][ni][2] + b0v) * mk1);
                vt1[s_ + 8] = f2tf((R.c[mi][ni][3] + b1v) * mk1);
            }
        }
    }
}

// ---------------- output GEMM ----------------
__global__ __launch_bounds__(256, 2)
void k_out(const float* __restrict__ bo, float* __restrict__ out) {
    extern __shared__ float smq[];
    int n0 = blockIdx.x * 128, m0 = blockIdx.y * 128;
    int tid = threadIdx.x;
    int wid = tid >> 5, lane = tid & 31, g = lane >> 2, tig = lane & 3;
    int wm = wid >> 1, wn = wid & 1;

    GemmOut R;
    gemm_body(g_aon, g_Wt + (size_t)3 * DD * DD, m0, n0, smq, R);

    #pragma unroll
    for (int mi = 0; mi < 2; mi++) {
        int r0 = m0 + wm * 32 + mi * 16 + g;
        #pragma unroll
        for (int ni = 0; ni < 8; ni++) {
            int col = n0 + wn * 64 + ni * 8 + tig * 2;
            float b0v = bo[col], b1v = bo[col + 1];
            float2 a0 = *(const float2*)(g_ao + (size_t)r0 * 512 + col);
            float2 a1 = *(const float2*)(g_ao + (size_t)(r0 + 8) * 512 + col);
            float2 o0 = make_float2(a0.x + fmaxf(R.c[mi][ni][0] + b0v, 0.f),
                                    a0.y + fmaxf(R.c[mi][ni][1] + b1v, 0.f));
            float2 o1 = make_float2(a1.x + fmaxf(R.c[mi][ni][2] + b0v, 0.f),
                                    a1.y + fmaxf(R.c[mi][ni][3] + b1v, 0.f));
            *(float2*)(out + (size_t)r0 * 512 + col)       = o0;
            *(float2*)(out + (size_t)(r0 + 8) * 512 + col) = o1;
        }
    }
}

// ---------------- attention: 4-deep pipelines, 64-row chunks ----------------
__global__ __launch_bounds__(512)
void k_attn(const float* __restrict__ Q, float* __restrict__ w_out) {
    extern __shared__ float sm[];
    float*    sc  = sm;                            // 32*1036
    unsigned* scU = (unsigned*)sc;
    float*    kvb = sm + 32 * SCP;                 // 4 * KVW
    unsigned* qs  = (unsigned*)(kvb + 4 * KVW);    // 32*68
    float*    red = (float*)(qs + 32 * 68);        // 32

    int tid = threadIdx.x;
    int wid = tid >> 5, lane = tid & 31, g = lane >> 2, tig = lane & 3;
    int m2 = lane >> 3, r8 = lane & 7;
    int bh = blockIdx.y, b = bh >> 3, h = bh & 7;
    int q0 = blockIdx.x * 32;
    size_t baseQ = ((size_t)b * SS + q0) * DD + h * HD;
    size_t baseK = ((size_t)b * SS) * DD + h * HD;
    size_t baseVt = (size_t)bh * HD * SS;
    const int bS = b * SS;

    unsigned uKV[4];
    #pragma unroll
    for (int i = 0; i < 4; i++) uKV[i] = cvta_s(kvb + i * KVW);
    unsigned uQS = cvta_s(qs), uSC = cvta_s(sc);

    int lr2 = tid >> 4, lc4 = tid & 15;   // loader: 64 rows x 16 float4 x2 per thread... (2 iters of 512)

    // K prologue: chunks 0..2 (64 keys each)
    #pragma unroll
    for (int p = 0; p < 3; p++) {
        #pragma unroll
        for (int i = 0; i < 2; i++) {
            int f = tid + 512 * i;
            int row = f >> 4, c4 = f & 15;
            CP16(uKV[p] + (row * 68 + c4 * 4) * 4,
                 g_Kp + baseK + (size_t)(p * 64 + row) * DD + c4 * 4);
        }
        CP_COMMIT();
    }

    // q tile -> smem (already tf32 bits)
    {
        int r = tid >> 4, c4 = tid & 15;
        *(uint4*)&qs[r * 68 + c4 * 4] =
            *(const uint4*)(g_Qp + baseQ + (size_t)r * DD + c4 * 4);
    }
    __syncthreads();

    // preload Q fragments (per warp: m16 x k64)
    int nslot = wid >> 1, mh = wid & 1;
    unsigned areg[8][4];
    {
        int rowQ = (mh * 16 + (m2 & 1) * 8 + r8) * 68 + (m2 >> 1) * 4;
        #pragma unroll
        for (int s = 0; s < 8; s++)
            ldsm4(uQS + (rowQ + s * 8) * 4, areg[s][0], areg[s][1], areg[s][2], areg[s][3]);
    }

    // ---- scores: 16 chunks of 64 keys; warp = m16 x n8 ----
    int rowKB = (nslot * 8 + r8) * 68 + m2 * 4;   // m2 selects k-segment (4 mats along k)
    for (int kt = 0; kt < 16; kt++) {
        CP_WAIT2();
        __syncthreads();
        if (kt + 3 < 16) {
            unsigned nxt = uKV[(kt + 3) & 3];
            #pragma unroll
            for (int i = 0; i < 2; i++) {
                int f = tid + 512 * i;
                int row = f >> 4, c4 = f & 15;
                CP16(nxt + (row * 68 + c4 * 4) * 4,
                     g_Kp + baseK + (size_t)((kt + 3) * 64 + row) * DD + c4 * 4);
            }
        }
        CP_COMMIT();

        unsigned uKVf = uKV[kt & 3];
        float cc[4] = {0.f, 0.f, 0.f, 0.f};
        #pragma unroll
        for (int s16 = 0; s16 < 4; s16++) {
            unsigned b0, b1, b2, b3;
            ldsm4(uKVf + (rowKB + s16 * 16) * 4, b0, b1, b2, b3);
            mma8(cc, areg[2*s16][0],   areg[2*s16][1],   areg[2*s16][2],   areg[2*s16][3],   b0, b1);
            mma8(cc, areg[2*s16+1][0], areg[2*s16+1][1], areg[2*s16+1][2], areg[2*s16+1][3], b2, b3);
        }
        int gc = kt * 64 + nslot * 8 + tig * 2;
        bool k0v = g_mask[bS + gc] != 0;
        bool k1v = g_mask[bS + gc + 1] != 0;
        int r = mh * 16 + g;
        float2 v0 = make_float2(k0v ? cc[0] * 0.125f : -1e30f,
                                k1v ? cc[1] * 0.125f : -1e30f);
        float2 v1 = make_float2(k0v ? cc[2] * 0.125f : -1e30f,
                                k1v ? cc[3] * 0.125f : -1e30f);
        *(float2*)&sc[r * SCP + gc]       = v0;
        *(float2*)&sc[(r + 8) * SCP + gc] = v1;
    }

    // V^T prologue: chunks 0..2 (64 d-rows x 64 s-words each)
    #pragma unroll
    for (int p = 0; p < 3; p++) {
        #pragma unroll
        for (int i = 0; i < 2; i++) {
            int f = tid + 512 * i;
            int row = f >> 4, c4 = f & 15;
            CP16(uKV[p] + (row * 68 + c4 * 4) * 4,
                 g_Vt + baseVt + (size_t)row * SS + p * 64 + c4 * 4);
        }
        CP_COMMIT();
    }
    __syncthreads();   // all score-panel writes visible

    // ---- softmax (no max pass) + fused w-write + tf32 convert ----
    {
        int row = tid >> 4, l = tid & 15;
        float* srow = sc + row * SCP;
        float sum = 0.f;
        #pragma unroll
        for (int j = 0; j < 16; j++) {
            float4 v = *(float4*)&srow[(l + 16 * j) * 4];
            v.x = __expf(v.x); v.y = __expf(v.y); v.z = __expf(v.z); v.w = __expf(v.w);
            sum += v.x + v.y + v.z + v.w;
            *(float4*)&srow[(l + 16 * j) * 4] = v;
        }
        #pragma unroll
        for (int o = 8; o > 0; o >>= 1) sum += __shfl_xor_sync(0xffffffffu, sum, o);
        float inv = g_mask[bS + q0 + row] ? (1.0f / sum) : 0.f;

        float* wrow = w_out + ((size_t)bh * SS + q0 + row) * SS;
        unsigned* urow = scU + row * SCP;
        #pragma unroll
        for (int j = 0; j < 16; j++) {
            int c = (l + 16 * j) * 4;
            float4 v = *(float4*)&srow[c];
            v.x *= inv; v.y *= inv; v.z *= inv; v.w *= inv;
            *(float4*)(wrow + c) = v;
            uint4 u; u.x = f2tf(v.x); u.y = f2tf(v.y); u.z = f2tf(v.z); u.w = f2tf(v.w);
            *(uint4*)&urow[c] = u;
        }
    }
    __syncthreads();

    // ---- attnV: 16 chunks of 64 s; 16 warps = 8 k-splits x 2 n-slots ----
    int ksl = wid & 7, nsl = wid >> 3;
    int rowPA0 = (     (m2 & 1) * 8 + r8) * SCP + (m2 >> 1) * 4;
    int rowPA1 = (16 + (m2 & 1) * 8 + r8) * SCP + (m2 >> 1) * 4;
    int rowVB0 = (nsl * 32 +      (m2 >> 1) * 8 + r8) * 68 + (m2 & 1) * 4;
    int rowVB1 = (nsl * 32 + 16 + (m2 >> 1) * 8 + r8) * 68 + (m2 & 1) * 4;

    float acc[2][4][4];
    #pragma unroll
    for (int mi = 0; mi < 2; mi++)
        #pragma unroll
        for (int nf = 0; nf < 4; nf++)
            #pragma unroll
            for (int j = 0; j < 4; j++) acc[mi][nf][j] = 0.f;

    for (int vt = 0; vt < 16; vt++) {
        CP_WAIT2();
        __syncthreads();
        if (vt + 3 < 16) {
            unsigned nxt = uKV[(vt + 3) & 3];
            #pragma unroll
            for (int i = 0; i < 2; i++) {
                int f = tid + 512 * i;
                int row = f >> 4, c4 = f & 15;
                CP16(nxt + (row * 68 + c4 * 4) * 4,
                     g_Vt + baseVt + (size_t)row * SS + (vt + 3) * 64 + c4 * 4);
            }
        }
        CP_COMMIT();

        unsigned uKVf = uKV[vt & 3];
        int kk = vt * 64 + ksl * 8;   // panel col
        int kl = ksl * 8;             // buffer col
        unsigned a[2][4], bb[4][2];
        ldsm4(uSC + (rowPA0 + kk) * 4, a[0][0], a[0][1], a[0][2], a[0][3]);
        ldsm4(uSC + (rowPA1 + kk) * 4, a[1][0], a[1][1], a[1][2], a[1][3]);
        ldsm4(uKVf + (rowVB0 + kl) * 4, bb[0][0], bb[0][1], bb[1][0], bb[1][1]);
        ldsm4(uKVf + (rowVB1 + kl) * 4, bb[2][0], bb[2][1], bb[3][0], bb[3][1]);
        #pragma unroll
        for (int nf = 0; nf < 4; nf++) {
            mma8(acc[0][nf], a[0][0], a[0][1], a[0][2], a[0][3], bb[nf][0], bb[nf][1]);
            mma8(acc[1][nf], a[1][0], a[1][1], a[1][2], a[1][3], bb[nf][0], bb[nf][1]);
        }
    }
    __syncthreads();

    // ---- reduce 8 k-splits via kvb (8 regions of 32x68 = 17408 words, fits exactly) ----
    float* at = kvb;
    #pragma unroll
    for (int mi = 0; mi < 2; mi++) {
        int r = mi * 16 + g;
        #pragma unroll
        for (int nf = 0; nf < 4; nf++) {
            int col = nsl * 32 + nf * 8 + tig * 2;
            *(float2*)&at[ksl * 2176 + r * 68 + col]       = make_float2(acc[mi][nf][0], acc[mi][nf][1]);
            *(float2*)&at[ksl * 2176 + (r + 8) * 68 + col] = make_float2(acc[mi][nf][2], acc[mi][nf][3]);
        }
    }
    __syncthreads();

    // ---- epilogue: attn_out = attn + Q; stats2 ----
    {
        int lr = tid >> 4;
        float4 o = make_float4(0.f, 0.f, 0.f, 0.f);
        #pragma unroll
        for (int k = 0; k < 8; k++) {
            float4 p = *(const float4*)&at[k * 2176 + lr * 68 + lc4 * 4];
            o.x += p.x; o.y += p.y; o.z += p.z; o.w += p.w;
        }
        size_t gaddr = baseQ + (size_t)lr * DD + lc4 * 4;
        float4 q4 = *(const float4*)(Q + gaddr);
        o.x += q4.x; o.y += q4.y; o.z += q4.z; o.w += q4.w;
        *(float4*)(g_ao + gaddr) = o;
        float t1 = o.x + o.y + o.z + o.w;
        float t2 = o.x*o.x + o.y*o.y + o.z*o.z + o.w*o.w;
        #pragma unroll
        for (int off = 16; off > 0; off >>= 1) {
            t1 += __shfl_xor_sync(0xffffffffu, t1, off);
            t2 += __shfl_xor_sync(0xffffffffu, t2, off);
        }
        if (lane == 0) { red[wid] = t1; red[16 + wid] = t2; }
    }
    __syncthreads();
    if (tid == 0) {
        float S1 = 0.f, S2 = 0.f;
        #pragma unroll
        for (int i = 0; i < 16; i++) { S1 += red[i]; S2 += red[16 + i]; }
        atomicAdd(&g_sum2[b], S1);
        atomicAdd(&g_sq2[b], S2);
    }
}

// ---------------- launch ----------------
extern "C" void kernel_launch(void* const* d_in, const int* in_sizes, int n_in,
                              void* d_out, int out_size) {
    const float* Q  = (const float*)d_in[0];
    const float* Wq = (const float*)d_in[1];
    const float* bq = (const float*)d_in[2];
    const float* Wk = (const float*)d_in[3];
    const float* bk = (const float*)d_in[4];
    const float* Wv = (const float*)d_in[5];
    const float* bv = (const float*)d_in[6];
    const float* Wo = (const float*)d_in[7];
    const float* bo = (const float*)d_in[8];

    float* out = (float*)d_out;
    float* w   = out + (size_t)BB * SS * DD;

    float* g_ao_ptr;  cudaGetSymbolAddress((void**)&g_ao_ptr,  g_ao);
    float* g_Qn_ptr;  cudaGetSymbolAddress((void**)&g_Qn_ptr,  g_Qn);
    float* g_aon_ptr; cudaGetSymbolAddress((void**)&g_aon_ptr, g_aon);

    const int GEMM_SMEM = 4 * 4608 * 4;                             // 73728 B
    const int ATTN_SMEM = (32 * SCP + 4 * KVW + 32 * 68 + 32) * 4;  // ~211 KB
    cudaFuncSetAttribute(k_qkv,  cudaFuncAttributeMaxDynamicSharedMemorySize, GEMM_SMEM);
    cudaFuncSetAttribute(k_out,  cudaFuncAttributeMaxDynamicSharedMemorySize, GEMM_SMEM);
    cudaFuncSetAttribute(k_attn, cudaFuncAttributeMaxDynamicSharedMemorySize, ATTN_SMEM);

    k_cvtW<<<dim3(16, 16, 4), 256>>>(Wq, Wk, Wv, Wo);
    k_maskstats<<<NROWS, 128>>>(Q);
    k_norm<<<NROWS, 128>>>(Q, g_Qn_ptr, 0);
    k_qkv<<<dim3(4, 64, 3), 256, GEMM_SMEM>>>(bq, bk, bv);
    k_attn<<<dim3(32, 64), 512, ATTN_SMEM>>>(Q, w);
    k_norm<<<NROWS, 128>>>(g_ao_ptr, g_aon_ptr, 1);
    k_out<<<dim3(4, 64), 256, GEMM_SMEM>>>(bo, out);
}